// round 1
// baseline (speedup 1.0000x reference)
#include <cuda_runtime.h>

#define N_NODES 40000
#define N_EDGES 640000

// Scratch (allocation-free rule: __device__ globals)
__device__ float g_sv[N_NODES * 128];    // lin1 output: [s(32) | vx(32) | vy(32) | vz(32)] per node
__device__ float g_acc[N_NODES * 256];   // edge aggregation: [s0(32)|s1(32)| vx(64)|vy(64)|vz(64)]

__device__ __forceinline__ float silu_n(float x) {
    return (x / (1.0f + __expf(-x))) * 1.6791767923989418f;
}

// ---------------------------------------------------------------------------
// K0: zero the accumulator
// ---------------------------------------------------------------------------
__global__ void zero_acc_kernel() {
    int idx = blockIdx.x * blockDim.x + threadIdx.x;
    const int total = N_NODES * 256 / 4;
    float4 z = make_float4(0.f, 0.f, 0.f, 0.f);
    if (idx < total) ((float4*)g_acc)[idx] = z;
}

// ---------------------------------------------------------------------------
// K1: lin1 — per node: s' = s @ W1s/sqrt(32), v' = einsum(v, W1v/sqrt(32))
// Output stored component-major in g_sv for coalesced edge gathers.
// One warp per node, lane = output mul index w.
// ---------------------------------------------------------------------------
__global__ void lin1_kernel(const float* __restrict__ ni,
                            const float* __restrict__ w1s,
                            const float* __restrict__ w1v) {
    __shared__ float sWs[1024], sWv[1024];
    __shared__ float srow[8][128];
    int tid = threadIdx.x;
    const float sc = 0.17677669529663687f;  // 1/sqrt(32)
    for (int i = tid; i < 1024; i += 256) { sWs[i] = w1s[i] * sc; sWv[i] = w1v[i] * sc; }
    __syncthreads();

    int warp = tid >> 5, lane = tid & 31;
    int node = blockIdx.x * 8 + warp;
    if (node >= N_NODES) return;

    // stage input row (128 floats) into shared, coalesced
    ((float4*)srow[warp])[lane] = ((const float4*)(ni + (size_t)node * 128))[lane];
    __syncwarp();

    float s = 0.f, v0 = 0.f, v1 = 0.f, v2 = 0.f;
#pragma unroll
    for (int u = 0; u < 32; u++) {
        float su = srow[warp][u];
        float a0 = srow[warp][32 + u * 3 + 0];
        float a1 = srow[warp][32 + u * 3 + 1];
        float a2 = srow[warp][32 + u * 3 + 2];
        float ws = sWs[u * 32 + lane];
        float wv = sWv[u * 32 + lane];
        s  = fmaf(su, ws, s);
        v0 = fmaf(a0, wv, v0);
        v1 = fmaf(a1, wv, v1);
        v2 = fmaf(a2, wv, v2);
    }
    float* o = g_sv + (size_t)node * 128;
    o[lane]      = s;
    o[32 + lane] = v0;
    o[64 + lane] = v1;
    o[96 + lane] = v2;
}

// ---------------------------------------------------------------------------
// K2: edge kernel — one warp per group of 4 edges (lane = mul index u).
// Fused MLP (8 -> 64 -> silu -> 128) with shared-staged weights, then
// gather src features (L2-resident) and atomicAdd into g_acc at dst.
// ---------------------------------------------------------------------------
#define EPW 4
__global__ void edge_kernel(const int*    __restrict__ esrc,
                            const int*    __restrict__ edst,
                            const float4* __restrict__ eattr,
                            const float4* __restrict__ escal,
                            const float*  __restrict__ fw1,
                            const float*  __restrict__ fw2) {
    __shared__ float sF1[512];    // fc_w1 / sqrt(8)
    __shared__ float sF2[8192];   // fc_w2 / 8
    int tid = threadIdx.x;
    for (int i = tid; i < 512;  i += 256) sF1[i] = fw1[i] * 0.3535533905932738f;
    for (int i = tid; i < 8192; i += 256) sF2[i] = fw2[i] * 0.125f;
    __syncthreads();

    int lane = tid & 31;
    int warp_global = blockIdx.x * (blockDim.x >> 5) + (tid >> 5);
    int nwarps = gridDim.x * (blockDim.x >> 5);
    const int ngroups = N_EDGES / EPW;

    for (int g = warp_global; g < ngroups; g += nwarps) {
        int e0 = g * EPW;
        float h0[EPW], h1[EPW], es[EPW], evx[EPW], evy[EPW], evz[EPW];
        int src[EPW], dst[EPW];

        // Phase A: per-edge loads + first MLP layer (lane computes h[lane], h[lane+32])
#pragma unroll
        for (int e = 0; e < EPW; e++) {
            int ed = e0 + e;
            src[e] = esrc[ed];
            dst[e] = edst[ed];
            float4 ea = eattr[ed];
            es[e] = ea.x; evx[e] = ea.y; evy[e] = ea.z; evz[e] = ea.w;
            float4 sA = escal[ed * 2 + 0];
            float4 sB = escal[ed * 2 + 1];
            float sc8[8] = {sA.x, sA.y, sA.z, sA.w, sB.x, sB.y, sB.z, sB.w};
            float a0 = 0.f, a1 = 0.f;
#pragma unroll
            for (int i = 0; i < 8; i++) {
                a0 = fmaf(sc8[i], sF1[i * 64 + lane],      a0);
                a1 = fmaf(sc8[i], sF1[i * 64 + 32 + lane], a1);
            }
            h0[e] = silu_n(a0);
            h1[e] = silu_n(a1);
        }

        // Phase B: second MLP layer. w_k[lane] = sum_j h[j] * fc_w2[j][k*32+lane]
        float w0[EPW] = {0.f, 0.f, 0.f, 0.f};
        float w1[EPW] = {0.f, 0.f, 0.f, 0.f};
        float w2[EPW] = {0.f, 0.f, 0.f, 0.f};
        float w3[EPW] = {0.f, 0.f, 0.f, 0.f};
#pragma unroll 4
        for (int j = 0; j < 32; j++) {
            const float* b = sF2 + j * 128 + lane;
            const float* c = sF2 + (j + 32) * 128 + lane;
            float b0 = b[0], b1 = b[32], b2 = b[64], b3 = b[96];
            float c0 = c[0], c1 = c[32], c2 = c[64], c3 = c[96];
#pragma unroll
            for (int e = 0; e < EPW; e++) {
                float hj = __shfl_sync(0xffffffffu, h0[e], j);
                float gj = __shfl_sync(0xffffffffu, h1[e], j);
                w0[e] = fmaf(hj, b0, fmaf(gj, c0, w0[e]));
                w1[e] = fmaf(hj, b1, fmaf(gj, c1, w1[e]));
                w2[e] = fmaf(hj, b2, fmaf(gj, c2, w2[e]));
                w3[e] = fmaf(hj, b3, fmaf(gj, c3, w3[e]));
            }
        }

        // Phase C: gather src (component-major, coalesced), tensor product, scatter-add
#pragma unroll
        for (int e = 0; e < EPW; e++) {
            const float* r = g_sv + (size_t)src[e] * 128;
            float se = r[lane];
            float vx = r[32 + lane];
            float vy = r[64 + lane];
            float vz = r[96 + lane];
            float dotv = fmaf(vx, evx[e], fmaf(vy, evy[e], vz * evz[e]));
            float ms0 = w0[e] * se * es[e];
            float ms1 = w3[e] * dotv * 0.5773502691896258f;  // 1/sqrt(3)
            float aa  = w1[e] * se;
            float bb  = w2[e] * es[e];
            float* ar = g_acc + (size_t)dst[e] * 256;
            atomicAdd(ar + lane,            ms0);
            atomicAdd(ar + 32 + lane,       ms1);
            atomicAdd(ar + 64 + lane,       aa * evx[e]);   // v0, i=0 (u=lane)
            atomicAdd(ar + 128 + lane,      aa * evy[e]);   // v0, i=1
            atomicAdd(ar + 192 + lane,      aa * evz[e]);   // v0, i=2
            atomicAdd(ar + 64 + 32 + lane,  bb * vx);       // v1, i=0 (u=32+lane)
            atomicAdd(ar + 128 + 32 + lane, bb * vy);       // v1, i=1
            atomicAdd(ar + 192 + 32 + lane, bb * vz);       // v1, i=2
        }
    }
}

// ---------------------------------------------------------------------------
// K3: lin2 — per node: out_s = ns @ W2s*(inv/fan), out_v = einsum(nv, W2v*(inv/fan))
// One warp per node, lane = output mul index w. inv=0.25, fan=8 folded.
// ---------------------------------------------------------------------------
__global__ void lin2_kernel(const float* __restrict__ w2s,
                            const float* __restrict__ w2v,
                            float* __restrict__ out) {
    __shared__ float sWs[2048], sWv[2048];
    __shared__ float srow[8][256];
    int tid = threadIdx.x;
    const float sc = 0.03125f;  // (1/sqrt(16)) / sqrt(64)
    for (int i = tid; i < 2048; i += 256) { sWs[i] = w2s[i] * sc; sWv[i] = w2v[i] * sc; }
    __syncthreads();

    int warp = tid >> 5, lane = tid & 31;
    int node = blockIdx.x * 8 + warp;
    if (node >= N_NODES) return;

    const float4* ar = (const float4*)(g_acc + (size_t)node * 256);
    ((float4*)srow[warp])[lane]      = ar[lane];
    ((float4*)srow[warp])[lane + 32] = ar[lane + 32];
    __syncwarp();

    float s = 0.f, v0 = 0.f, v1 = 0.f, v2 = 0.f;
#pragma unroll
    for (int u = 0; u < 64; u++) {
        float ws = sWs[u * 32 + lane];
        float wv = sWv[u * 32 + lane];
        s  = fmaf(srow[warp][u],       ws, s);
        v0 = fmaf(srow[warp][64 + u],  wv, v0);
        v1 = fmaf(srow[warp][128 + u], wv, v1);
        v2 = fmaf(srow[warp][192 + u], wv, v2);
    }
    float* o = out + (size_t)node * 128;
    o[lane] = s;
    o[32 + lane * 3 + 0] = v0;
    o[32 + lane * 3 + 1] = v1;
    o[32 + lane * 3 + 2] = v2;
}

// ---------------------------------------------------------------------------
extern "C" void kernel_launch(void* const* d_in, const int* in_sizes, int n_in,
                              void* d_out, int out_size) {
    const float* node_input = (const float*)d_in[0];
    // d_in[1] = node_attr (all ones, unused by reference)
    const int*   esrc  = (const int*)d_in[2];
    const int*   edst  = (const int*)d_in[3];
    const float* eattr = (const float*)d_in[4];
    const float* escal = (const float*)d_in[5];
    const float* w1s   = (const float*)d_in[6];
    const float* w1v   = (const float*)d_in[7];
    const float* fw1   = (const float*)d_in[8];
    const float* fw2   = (const float*)d_in[9];
    const float* w2s   = (const float*)d_in[10];
    const float* w2v   = (const float*)d_in[11];
    float* out = (float*)d_out;

    zero_acc_kernel<<<(N_NODES * 256 / 4 + 255) / 256, 256>>>();
    lin1_kernel<<<N_NODES / 8, 256>>>(node_input, w1s, w1v);
    edge_kernel<<<888, 256>>>(esrc, edst, (const float4*)eattr,
                              (const float4*)escal, fw1, fw2);
    lin2_kernel<<<N_NODES / 8, 256>>>(w2s, w2v, out);
}

// round 2
// speedup vs baseline: 1.2495x; 1.2495x over previous
#include <cuda_runtime.h>

#define N_NODES 40000
#define N_EDGES 640000

// Scratch (allocation-free rule: __device__ globals)
__device__ float g_sv[N_NODES * 128];    // lin1 output: [s(32) | vx(32) | vy(32) | vz(32)] per node
// edge aggregation, quad-interleaved: acc[node][u][c], u in [0,64), c=(s,vx,vy,vz)
__device__ float g_acc[N_NODES * 256];

__device__ __forceinline__ float silu_n(float x) {
    return (x / (1.0f + __expf(-x))) * 1.6791767923989418f;
}

// ---- f32x2 packed helpers (Blackwell) -------------------------------------
__device__ __forceinline__ unsigned long long pk(float a, float b) {
    unsigned long long r;
    asm("mov.b64 %0, {%1,%2};" : "=l"(r) : "f"(a), "f"(b));
    return r;
}
__device__ __forceinline__ void fma2(unsigned long long& d,
                                     unsigned long long a, unsigned long long b) {
    asm("fma.rn.f32x2 %0, %1, %2, %0;" : "+l"(d) : "l"(a), "l"(b));
}
__device__ __forceinline__ float2 unpk(unsigned long long v) {
    float2 r;
    asm("mov.b64 {%0,%1}, %2;" : "=f"(r.x), "=f"(r.y) : "l"(v));
    return r;
}
__device__ __forceinline__ void red4(float* p, float a, float b, float c, float d) {
    asm volatile("red.global.add.v4.f32 [%0], {%1,%2,%3,%4};"
                 :: "l"(p), "f"(a), "f"(b), "f"(c), "f"(d) : "memory");
}

// ---------------------------------------------------------------------------
// K0: zero the accumulator
// ---------------------------------------------------------------------------
__global__ void zero_acc_kernel() {
    int idx = blockIdx.x * blockDim.x + threadIdx.x;
    const int total = N_NODES * 256 / 4;
    float4 z = make_float4(0.f, 0.f, 0.f, 0.f);
    if (idx < total) ((float4*)g_acc)[idx] = z;
}

// ---------------------------------------------------------------------------
// K1: lin1 — per node: s' = s @ W1s/sqrt(32), v' = einsum(v, W1v/sqrt(32))
// Output stored component-major in g_sv for coalesced edge gathers.
// ---------------------------------------------------------------------------
__global__ void lin1_kernel(const float* __restrict__ ni,
                            const float* __restrict__ w1s,
                            const float* __restrict__ w1v) {
    __shared__ float sWs[1024], sWv[1024];
    __shared__ float srow[8][128];
    int tid = threadIdx.x;
    const float sc = 0.17677669529663687f;  // 1/sqrt(32)
    for (int i = tid; i < 1024; i += 256) { sWs[i] = w1s[i] * sc; sWv[i] = w1v[i] * sc; }
    __syncthreads();

    int warp = tid >> 5, lane = tid & 31;
    int node = blockIdx.x * 8 + warp;
    if (node >= N_NODES) return;

    ((float4*)srow[warp])[lane] = ((const float4*)(ni + (size_t)node * 128))[lane];
    __syncwarp();

    float s = 0.f, v0 = 0.f, v1 = 0.f, v2 = 0.f;
#pragma unroll
    for (int u = 0; u < 32; u++) {
        float su = srow[warp][u];
        float a0 = srow[warp][32 + u * 3 + 0];
        float a1 = srow[warp][32 + u * 3 + 1];
        float a2 = srow[warp][32 + u * 3 + 2];
        float ws = sWs[u * 32 + lane];
        float wv = sWv[u * 32 + lane];
        s  = fmaf(su, ws, s);
        v0 = fmaf(a0, wv, v0);
        v1 = fmaf(a1, wv, v1);
        v2 = fmaf(a2, wv, v2);
    }
    float* o = g_sv + (size_t)node * 128;
    o[lane]      = s;
    o[32 + lane] = v0;
    o[64 + lane] = v1;
    o[96 + lane] = v2;
}

// ---------------------------------------------------------------------------
// K2: edge kernel — one warp per group of 8 edges (lane = mul index u).
// MLP layer2 via packed f32x2 FMA; h broadcast through shared (no shuffles);
// weights packed [j][lane][4] for single-LDS.128 fetch; output scatter via
// 2x red.global.add.v4.f32 per edge-lane into quad-interleaved accumulator.
// ---------------------------------------------------------------------------
#define EPW 8
__global__ void __launch_bounds__(128, 4)
edge_kernel(const int*    __restrict__ esrc,
            const int*    __restrict__ edst,
            const float4* __restrict__ eattr,
            const float4* __restrict__ escal,
            const float*  __restrict__ fw1,
            const float*  __restrict__ fw2) {
    __shared__ float sF1[512];        // fc_w1 / sqrt(8), [i][64]
    __shared__ float sF2p[8192];      // fc_w2 / 8, packed [j][lane][4]
    __shared__ float h_sh[4][64 * EPW];  // per-warp h, [j][e]
    int tid = threadIdx.x;
    for (int i = tid; i < 512; i += 128) sF1[i] = fw1[i] * 0.3535533905932738f;
    for (int i = tid; i < 8192; i += 128) {
        int j = i >> 7;            // 0..63
        int r = i & 127;
        int l = r >> 2, k = r & 3; // lane, output-block
        sF2p[i] = fw2[j * 128 + k * 32 + l] * 0.125f;
    }
    __syncthreads();

    int lane = tid & 31, warp = tid >> 5;
    float* hs = h_sh[warp];
    int wg = blockIdx.x * 4 + warp;
    int nw = gridDim.x * 4;
    const int ngroups = N_EDGES / EPW;

    for (int g = wg; g < ngroups; g += nw) {
        int e0 = g * EPW;
        int src[EPW], dst[EPW];
        float es[EPW], evx[EPW], evy[EPW], evz[EPW];
        float h0[EPW], h1[EPW];

        // Phase A: loads + first MLP layer (lane computes h[lane], h[lane+32])
#pragma unroll
        for (int e = 0; e < EPW; e++) {
            int ed = e0 + e;
            src[e] = esrc[ed];
            dst[e] = edst[ed];
            float4 ea = eattr[ed];
            es[e] = ea.x; evx[e] = ea.y; evy[e] = ea.z; evz[e] = ea.w;
            float4 sA = escal[ed * 2 + 0];
            float4 sB = escal[ed * 2 + 1];
            float sc8[8] = {sA.x, sA.y, sA.z, sA.w, sB.x, sB.y, sB.z, sB.w};
            float a0 = 0.f, a1 = 0.f;
#pragma unroll
            for (int i = 0; i < 8; i++) {
                a0 = fmaf(sc8[i], sF1[i * 64 + lane],      a0);
                a1 = fmaf(sc8[i], sF1[i * 64 + 32 + lane], a1);
            }
            h0[e] = silu_n(a0);
            h1[e] = silu_n(a1);
        }
        __syncwarp();  // previous iteration's readers of hs are done
        // stage h into shared: row j=lane gets h0, row j=32+lane gets h1
        ((float4*)hs)[lane * 2 + 0]      = make_float4(h0[0], h0[1], h0[2], h0[3]);
        ((float4*)hs)[lane * 2 + 1]      = make_float4(h0[4], h0[5], h0[6], h0[7]);
        ((float4*)hs)[64 + lane * 2 + 0] = make_float4(h1[0], h1[1], h1[2], h1[3]);
        ((float4*)hs)[64 + lane * 2 + 1] = make_float4(h1[4], h1[5], h1[6], h1[7]);
        __syncwarp();

        // Phase B: layer 2 with packed f32x2 FMA. w01[e]=(w0,w1), w23[e]=(w2,w3)
        unsigned long long w01[EPW], w23[EPW];
#pragma unroll
        for (int e = 0; e < EPW; e++) { w01[e] = 0ull; w23[e] = 0ull; }
#pragma unroll 8
        for (int j = 0; j < 64; j++) {
            float4 bw = ((const float4*)sF2p)[j * 32 + lane];  // per-lane weights
            unsigned long long b01 = pk(bw.x, bw.y);
            unsigned long long b23 = pk(bw.z, bw.w);
            float4 hA = ((const float4*)hs)[j * 2 + 0];  // broadcast h, e0..3
            float4 hB = ((const float4*)hs)[j * 2 + 1];  // e4..7
            float hv[EPW] = {hA.x, hA.y, hA.z, hA.w, hB.x, hB.y, hB.z, hB.w};
#pragma unroll
            for (int e = 0; e < EPW; e++) {
                unsigned long long hh = pk(hv[e], hv[e]);
                fma2(w01[e], hh, b01);
                fma2(w23[e], hh, b23);
            }
        }

        // Phase C: gather src (L2-resident), tensor product, vector scatter-add
#pragma unroll
        for (int e = 0; e < EPW; e++) {
            const float* r = g_sv + (size_t)src[e] * 128;
            float se = r[lane];
            float vx = r[32 + lane];
            float vy = r[64 + lane];
            float vz = r[96 + lane];
            float2 a01 = unpk(w01[e]);  // (w0, w1)
            float2 a23 = unpk(w23[e]);  // (w2, w3)
            float dotv = fmaf(vx, evx[e], fmaf(vy, evy[e], vz * evz[e]));
            float ms0 = a01.x * se * es[e];
            float ms1 = a23.y * dotv * 0.5773502691896258f;  // 1/sqrt(3)
            float aa  = a01.y * se;
            float bb  = a23.x * es[e];
            float* ar = g_acc + (size_t)dst[e] * 256;
            red4(ar + lane * 4,       ms0, aa * evx[e], aa * evy[e], aa * evz[e]);
            red4(ar + 128 + lane * 4, ms1, bb * vx,     bb * vy,     bb * vz);
        }
    }
}

// ---------------------------------------------------------------------------
// K3: lin2 — per node, quad-interleaved acc input, packed f32x2 FMA.
// ---------------------------------------------------------------------------
__global__ void lin2_kernel(const float* __restrict__ w2s,
                            const float* __restrict__ w2v,
                            float* __restrict__ out) {
    __shared__ float sW[4096];      // (ws,wv) pairs: [u][lane][2]
    __shared__ float srow[8][256];
    int tid = threadIdx.x;
    const float sc = 0.03125f;      // (1/sqrt(16)) / sqrt(64)
    for (int i = tid; i < 2048; i += 256) {
        sW[i * 2 + 0] = w2s[i] * sc;
        sW[i * 2 + 1] = w2v[i] * sc;
    }
    __syncthreads();

    int warp = tid >> 5, lane = tid & 31;
    int node = blockIdx.x * 8 + warp;
    if (node >= N_NODES) return;

    const float4* ar = (const float4*)(g_acc + (size_t)node * 256);
    ((float4*)srow[warp])[lane]      = ar[lane];
    ((float4*)srow[warp])[lane + 32] = ar[lane + 32];
    __syncwarp();

    unsigned long long acc0 = 0ull, acc1 = 0ull;   // (s,v0), (v1,v2)
#pragma unroll 8
    for (int u = 0; u < 64; u++) {
        float4 q = ((const float4*)srow[warp])[u];        // broadcast (s,vx,vy,vz)
        float2 wsv = ((const float2*)sW)[u * 32 + lane];  // (ws, wv)
        fma2(acc0, pk(q.x, q.y), pk(wsv.x, wsv.y));
        fma2(acc1, pk(q.z, q.w), pk(wsv.y, wsv.y));
    }
    float2 r0 = unpk(acc0), r1 = unpk(acc1);
    float* o = out + (size_t)node * 128;
    o[lane] = r0.x;
    o[32 + lane * 3 + 0] = r0.y;
    o[32 + lane * 3 + 1] = r1.x;
    o[32 + lane * 3 + 2] = r1.y;
}

// ---------------------------------------------------------------------------
extern "C" void kernel_launch(void* const* d_in, const int* in_sizes, int n_in,
                              void* d_out, int out_size) {
    const float* node_input = (const float*)d_in[0];
    // d_in[1] = node_attr (all ones, unused by reference)
    const int*   esrc  = (const int*)d_in[2];
    const int*   edst  = (const int*)d_in[3];
    const float* eattr = (const float*)d_in[4];
    const float* escal = (const float*)d_in[5];
    const float* w1s   = (const float*)d_in[6];
    const float* w1v   = (const float*)d_in[7];
    const float* fw1   = (const float*)d_in[8];
    const float* fw2   = (const float*)d_in[9];
    const float* w2s   = (const float*)d_in[10];
    const float* w2v   = (const float*)d_in[11];
    float* out = (float*)d_out;

    zero_acc_kernel<<<(N_NODES * 256 / 4 + 255) / 256, 256>>>();
    lin1_kernel<<<N_NODES / 8, 256>>>(node_input, w1s, w1v);
    edge_kernel<<<592, 128>>>(esrc, edst, (const float4*)eattr,
                              (const float4*)escal, fw1, fw2);
    lin2_kernel<<<N_NODES / 8, 256>>>(w2s, w2v, out);
}